// round 8
// baseline (speedup 1.0000x reference)
#include <cuda_runtime.h>
#include <cuda_bf16.h>
#include <mma.h>
#include <cstdint>

using namespace nvcuda;

#define NU_  200000
#define NM_  80000
#define H_   128
#define FD_  512
#define EMAX_ 2000000

// ======================= scratch =======================
static __device__ float g_bufA[NM_*H_];
static __device__ float g_bufB[NM_*H_];
static __device__ float g_bufC[NM_*H_];
static __device__ float g_bufD[NM_*H_];
static __device__ float g_bufE[NU_*H_];
static __device__ float g_bufF[NU_*H_];

static __device__ int g_off_u[NU_+1];
static __device__ int g_off_m[NM_+1];
static __device__ int g_deg_u[NU_];
static __device__ int g_deg_m[NM_];
static __device__ int g_cur_u[NU_];
static __device__ int g_cur_m[NM_];
static __device__ int g_adj_u[EMAX_];
static __device__ int g_adj_m[EMAX_];
static __device__ float g_c1[H_];
static __device__ float g_c2[H_];
static __device__ int g_bsum[1024];
static __device__ int g_bpre[1026];

// transposed bf16 weights: Wm_T [128,512] then 6 x [128,128] (n-major, k contiguous)
#define WT_WM    0
#define WT_R1UM  (128*512)
#define WT_L1MU  (WT_R1UM + 128*128)
#define WT_R2UM  (WT_L1MU + 128*128)
#define WT_L2MU  (WT_R2UM + 128*128)
#define WT_L2UM  (WT_L2MU + 128*128)
#define WT_R2MU  (WT_L2UM + 128*128)
#define WT_TOT   (WT_R2MU + 128*128)
static __device__ __nv_bfloat16 g_wThi[WT_TOT];
static __device__ __nv_bfloat16 g_wTlo[WT_TOT];

// ======================= graph build =======================
__global__ void k_zero()
{
    int i = blockIdx.x * blockDim.x + threadIdx.x;
    int stride = gridDim.x * blockDim.x;
    for (int j = i; j < NU_; j += stride) { g_deg_u[j] = 0; g_cur_u[j] = 0; }
    for (int j = i; j < NM_; j += stride) { g_deg_m[j] = 0; g_cur_m[j] = 0; }
}

__global__ void k_hist(const int* __restrict__ src, const int* __restrict__ dst, int E)
{
    int i = blockIdx.x * blockDim.x + threadIdx.x;
    int stride = gridDim.x * blockDim.x;
    for (int e = i; e < E; e += stride) {
        atomicAdd(&g_deg_u[src[e]], 1);
        atomicAdd(&g_deg_m[dst[e]], 1);
    }
}

// 3-phase parallel scan
__global__ void __launch_bounds__(1024) k_scanA(const int* __restrict__ deg, int* __restrict__ off,
                                                int n, int chunk)
{
    __shared__ int ws[32];
    int b = blockIdx.x, tid = threadIdx.x, lane = tid & 31, wid = tid >> 5;
    int i = b * chunk + tid;
    int v = (tid < chunk && i < n) ? deg[i] : 0;
    int x = v;
    #pragma unroll
    for (int o = 1; o < 32; o <<= 1) {
        int y = __shfl_up_sync(0xffffffffu, x, o);
        if (lane >= o) x += y;
    }
    if (lane == 31) ws[wid] = x;
    __syncthreads();
    if (wid == 0) {
        int w = ws[lane];
        int xs = w;
        #pragma unroll
        for (int o = 1; o < 32; o <<= 1) {
            int y = __shfl_up_sync(0xffffffffu, xs, o);
            if (lane >= o) xs += y;
        }
        ws[lane] = xs - w;
    }
    __syncthreads();
    int ex = ws[wid] + x - v;
    if (tid < chunk && i < n) off[i] = ex;
    if (tid == 1023) g_bsum[b] = ex + v;
}

__global__ void __launch_bounds__(1024) k_scanB(int nb)
{
    __shared__ int ws[32];
    int tid = threadIdx.x, lane = tid & 31, wid = tid >> 5;
    int v = (tid < nb) ? g_bsum[tid] : 0;
    int x = v;
    #pragma unroll
    for (int o = 1; o < 32; o <<= 1) {
        int y = __shfl_up_sync(0xffffffffu, x, o);
        if (lane >= o) x += y;
    }
    if (lane == 31) ws[wid] = x;
    __syncthreads();
    if (wid == 0) {
        int w = ws[lane];
        int xs = w;
        #pragma unroll
        for (int o = 1; o < 32; o <<= 1) {
            int y = __shfl_up_sync(0xffffffffu, xs, o);
            if (lane >= o) xs += y;
        }
        ws[lane] = xs - w;
    }
    __syncthreads();
    int ex = ws[wid] + x - v;
    if (tid < nb) g_bpre[tid] = ex;
    if (tid == 1023) g_bpre[nb] = ex + v;
}

__global__ void k_scanC(int* __restrict__ off, int n, int chunk, int nb)
{
    int i = blockIdx.x * blockDim.x + threadIdx.x;
    if (i < n) off[i] += g_bpre[i / chunk];
    else if (i == n) off[n] = g_bpre[nb];
}

__global__ void k_fill(const int* __restrict__ src, const int* __restrict__ dst, int E)
{
    int i = blockIdx.x * blockDim.x + threadIdx.x;
    int stride = gridDim.x * blockDim.x;
    for (int e = i; e < E; e += stride) {
        int s = src[e], d = dst[e];
        int pm = g_off_m[d] + atomicAdd(&g_cur_m[d], 1);
        g_adj_m[pm] = s;
        int pu = g_off_u[s] + atomicAdd(&g_cur_u[s], 1);
        g_adj_u[pu] = d;
    }
}

// ======================= tiny precompute =======================
__global__ void k_cvec(const float* __restrict__ u0,
                       const float* __restrict__ Wl1um,
                       const float* __restrict__ Wr1mu,
                       const float* __restrict__ bl1mu)
{
    int c = threadIdx.x;
    float s1 = 0.f, s2 = 0.f;
    #pragma unroll 8
    for (int k = 0; k < H_; k++) {
        float u = u0[k];
        s1 += u * Wl1um[k * H_ + c];
        s2 += u * Wr1mu[k * H_ + c];
    }
    g_c1[c] = s1;
    g_c2[c] = bl1mu[c] + s2;
}

// transpose+split fp32 weight W[K,128] -> hi/lo bf16 [128,K] (n-major)
__global__ void k_wprep(const float* __restrict__ W, int K, int dstOff)
{
    int i = blockIdx.x * blockDim.x + threadIdx.x;
    if (i >= K * 128) return;
    int n = i & 127, k = i >> 7;
    float x = W[k * 128 + n];
    __nv_bfloat16 h = __float2bfloat16(x);
    float r = x - __bfloat162float(h);
    g_wThi[dstOff + (size_t)n * K + k] = h;
    g_wTlo[dstOff + (size_t)n * K + k] = __float2bfloat16(r);
}

// ======================= wmma bf16 split GEMM =======================
// C[M,128] = A[M,K] @ W[K,128]; A fp32, W pre-split hi/lo bf16, transposed [128,K].
// D = Ahi*Whi + Ahi*Wlo + Alo*Whi, fp32 accumulate.
// Block tile 128x128, 8 warps of 32x64. K chunked by 64 through smem (A only).
// mode 0: raw; 1: +bias; 2: relu(+bias+(deg>0)*cvec); 3: +bias+addM (addM may alias C)
#define LDA 72                     // bf16 elems per A smem row (64 + 8 pad)
#define SM_A_HI   0
#define SM_A_LO   (128 * LDA * 2)          // 18432
#define SM_GEMM_TOT (128 * 128 * 4)        // 65536 (epilogue float region overlaps A)

__global__ void __launch_bounds__(256) k_hgemm(
    const float* __restrict__ A, int M, int K,
    const __nv_bfloat16* __restrict__ WThi, const __nv_bfloat16* __restrict__ WTlo,
    float* __restrict__ C, int mode,
    const float* __restrict__ bias, const float* __restrict__ cvec,
    const int* __restrict__ deg, const float* __restrict__ addM)
{
    extern __shared__ char smem[];
    __nv_bfloat16* sAhi = (__nv_bfloat16*)(smem + SM_A_HI);
    __nv_bfloat16* sAlo = (__nv_bfloat16*)(smem + SM_A_LO);
    float* sC = (float*)smem;

    int t = threadIdx.x;
    int wid = t >> 5;
    int warp_m = wid & 3;          // 0..3 -> rows warp_m*32
    int warp_n = wid >> 2;         // 0..1 -> cols warp_n*64
    int rowBase = blockIdx.x * 128;

    wmma::fragment<wmma::accumulator, 16, 16, 16, float> acc[2][4];
    #pragma unroll
    for (int i = 0; i < 2; i++)
        #pragma unroll
        for (int j = 0; j < 4; j++) wmma::fill_fragment(acc[i][j], 0.0f);

    int lrow = t >> 1;                 // 0..127
    int lcb  = (t & 1) * 32;           // 0 or 32
    int grow = rowBase + lrow;
    bool arowOk = grow < M;
    const float* Arow = A + (size_t)grow * K;

    int nch = K >> 6;
    for (int ch = 0; ch < nch; ch++) {
        int k0 = ch * 64;
        // ---- A chunk: 128 x 64 fp32 -> hi/lo bf16 into smem ----
        #pragma unroll
        for (int j = 0; j < 8; j++) {
            int col = lcb + j * 4;
            float4 v = arowOk ? *(const float4*)(Arow + k0 + col)
                              : make_float4(0.f, 0.f, 0.f, 0.f);
            __nv_bfloat162 h01, h23, l01, l23;
            h01.x = __float2bfloat16(v.x); h01.y = __float2bfloat16(v.y);
            h23.x = __float2bfloat16(v.z); h23.y = __float2bfloat16(v.w);
            l01.x = __float2bfloat16(v.x - __bfloat162float(h01.x));
            l01.y = __float2bfloat16(v.y - __bfloat162float(h01.y));
            l23.x = __float2bfloat16(v.z - __bfloat162float(h23.x));
            l23.y = __float2bfloat16(v.w - __bfloat162float(h23.y));
            int base = lrow * LDA + col;
            *(__nv_bfloat162*)&sAhi[base]     = h01;
            *(__nv_bfloat162*)&sAhi[base + 2] = h23;
            *(__nv_bfloat162*)&sAlo[base]     = l01;
            *(__nv_bfloat162*)&sAlo[base + 2] = l23;
        }
        __syncthreads();

        // ---- 4 k-steps of 16 ----
        #pragma unroll
        for (int ks = 0; ks < 4; ks++) {
            int kk = ks * 16;
            wmma::fragment<wmma::matrix_a, 16, 16, 16, __nv_bfloat16, wmma::row_major> ah[2], al[2];
            wmma::fragment<wmma::matrix_b, 16, 16, 16, __nv_bfloat16, wmma::col_major> bh[4], bl[4];
            #pragma unroll
            for (int i = 0; i < 2; i++) {
                int r0 = warp_m * 32 + i * 16;
                wmma::load_matrix_sync(ah[i], &sAhi[r0 * LDA + kk], LDA);
                wmma::load_matrix_sync(al[i], &sAlo[r0 * LDA + kk], LDA);
            }
            #pragma unroll
            for (int j = 0; j < 4; j++) {
                int n0 = warp_n * 64 + j * 16;
                const __nv_bfloat16* ph = WThi + (size_t)n0 * K + k0 + kk;
                const __nv_bfloat16* pl = WTlo + (size_t)n0 * K + k0 + kk;
                wmma::load_matrix_sync(bh[j], ph, K);
                wmma::load_matrix_sync(bl[j], pl, K);
            }
            #pragma unroll
            for (int i = 0; i < 2; i++)
                #pragma unroll
                for (int j = 0; j < 4; j++) {
                    wmma::mma_sync(acc[i][j], ah[i], bh[j], acc[i][j]);
                    wmma::mma_sync(acc[i][j], ah[i], bl[j], acc[i][j]);
                    wmma::mma_sync(acc[i][j], al[i], bh[j], acc[i][j]);
                }
        }
        __syncthreads();
    }

    // ---- epilogue: stage accumulators to smem, then modes ----
    #pragma unroll
    for (int i = 0; i < 2; i++)
        #pragma unroll
        for (int j = 0; j < 4; j++) {
            int r0 = warp_m * 32 + i * 16;
            int n0 = warp_n * 64 + j * 16;
            wmma::store_matrix_sync(&sC[r0 * 128 + n0], acc[i][j], 128, wmma::mem_row_major);
        }
    __syncthreads();

    int erow = t >> 1;
    int ecb  = (t & 1) * 64;
    int growE = rowBase + erow;
    if (growE < M) {
        float ind = 0.f;
        if (mode == 2) ind = (deg[growE] > 0) ? 1.f : 0.f;
        #pragma unroll
        for (int j = 0; j < 16; j++) {
            int c = ecb + j * 4;
            float4 o = *(float4*)&sC[erow * 128 + c];
            if (mode == 1) {
                float4 b4 = *(const float4*)&bias[c];
                o.x += b4.x; o.y += b4.y; o.z += b4.z; o.w += b4.w;
            } else if (mode == 2) {
                float4 b4 = *(const float4*)&bias[c];
                float4 cv = *(const float4*)&cvec[c];
                o.x = fmaxf(o.x + b4.x + ind * cv.x, 0.f);
                o.y = fmaxf(o.y + b4.y + ind * cv.y, 0.f);
                o.z = fmaxf(o.z + b4.z + ind * cv.z, 0.f);
                o.w = fmaxf(o.w + b4.w + ind * cv.w, 0.f);
            } else if (mode == 3) {
                float4 b4 = *(const float4*)&bias[c];
                float4 a2 = *(const float4*)&addM[(size_t)growE * 128 + c];
                o.x += b4.x + a2.x; o.y += b4.y + a2.y;
                o.z += b4.z + a2.z; o.w += b4.w + a2.w;
            }
            *(float4*)&C[(size_t)growE * 128 + c] = o;
        }
    }
}

// ======================= mean aggregation =======================
__global__ void __launch_bounds__(256) k_agg(
    const int* __restrict__ off, const int* __restrict__ adj,
    const float* __restrict__ X, float* __restrict__ out, int n, int mode,
    const float* __restrict__ cvec, const float* __restrict__ bias,
    const float* __restrict__ addM)
{
    int node = blockIdx.x * 8 + (threadIdx.x >> 5);
    int lane = threadIdx.x & 31;
    if (node >= n) return;
    int s = off[node], e = off[node + 1];
    float4 a0 = make_float4(0.f, 0.f, 0.f, 0.f);
    float4 a1 = make_float4(0.f, 0.f, 0.f, 0.f);
    int p = s;
    for (; p + 1 < e; p += 2) {
        int m0 = __ldg(&adj[p]);
        int m1 = __ldg(&adj[p + 1]);
        float4 v0 = *(const float4*)&X[(size_t)m0 * 128 + lane * 4];
        float4 v1 = *(const float4*)&X[(size_t)m1 * 128 + lane * 4];
        a0.x += v0.x; a0.y += v0.y; a0.z += v0.z; a0.w += v0.w;
        a1.x += v1.x; a1.y += v1.y; a1.z += v1.z; a1.w += v1.w;
    }
    if (p < e) {
        int m0 = __ldg(&adj[p]);
        float4 v0 = *(const float4*)&X[(size_t)m0 * 128 + lane * 4];
        a0.x += v0.x; a0.y += v0.y; a0.z += v0.z; a0.w += v0.w;
    }
    float4 acc = make_float4(a0.x + a1.x, a0.y + a1.y, a0.z + a1.z, a0.w + a1.w);
    float inv = (e > s) ? 1.f / (float)(e - s) : 0.f;
    acc.x *= inv; acc.y *= inv; acc.z *= inv; acc.w *= inv;

    float4 o = acc;
    if (mode == 0) {
        float4 c = *(const float4*)&cvec[lane * 4];
        o.x = fmaxf(acc.x + c.x, 0.f);
        o.y = fmaxf(acc.y + c.y, 0.f);
        o.z = fmaxf(acc.z + c.z, 0.f);
        o.w = fmaxf(acc.w + c.w, 0.f);
    } else if (mode == 2) {
        float4 b = *(const float4*)&bias[lane * 4];
        float4 a2 = *(const float4*)&addM[(size_t)node * 128 + lane * 4];
        o.x = acc.x + b.x + a2.x;
        o.y = acc.y + b.y + a2.y;
        o.z = acc.z + b.z + a2.z;
        o.w = acc.w + b.w + a2.w;
    }
    *(float4*)&out[(size_t)node * 128 + lane * 4] = o;
}

// ======================= final edge dot =======================
__global__ void __launch_bounds__(256) k_dot(
    const int* __restrict__ lu, const int* __restrict__ lm,
    const float* __restrict__ U, const float* __restrict__ Mo,
    float* __restrict__ out, int n)
{
    int e = blockIdx.x * 8 + (threadIdx.x >> 5);
    int lane = threadIdx.x & 31;
    if (e >= n) return;
    int u = lu[e], m = lm[e];
    float4 a = *(const float4*)&U [(size_t)u * 128 + lane * 4];
    float4 b = *(const float4*)&Mo[(size_t)m * 128 + lane * 4];
    float p = a.x * b.x + a.y * b.y + a.z * b.z + a.w * b.w;
    #pragma unroll
    for (int o = 16; o > 0; o >>= 1) p += __shfl_xor_sync(0xffffffffu, p, o);
    if (lane == 0) out[e] = p;
}

// ======================= launch =======================
extern "C" void kernel_launch(void* const* d_in, const int* in_sizes, int n_in,
                              void* d_out, int out_size)
{
    const float* movie_feats = (const float*)d_in[0];
    const float* user_init   = (const float*)d_in[1];
    const int*   edge_src    = (const int*)d_in[2];
    const int*   edge_dst    = (const int*)d_in[3];
    const int*   lbl_user    = (const int*)d_in[4];
    const int*   lbl_movie   = (const int*)d_in[5];
    const float* Wm     = (const float*)d_in[7];
    const float* bm     = (const float*)d_in[8];
    const float* Wl1_um = (const float*)d_in[9];
    const float* bl1_um = (const float*)d_in[10];
    const float* Wr1_um = (const float*)d_in[11];
    const float* Wl1_mu = (const float*)d_in[12];
    const float* bl1_mu = (const float*)d_in[13];
    const float* Wr1_mu = (const float*)d_in[14];
    const float* Wl2_um = (const float*)d_in[15];
    const float* bl2_um = (const float*)d_in[16];
    const float* Wr2_um = (const float*)d_in[17];
    const float* Wl2_mu = (const float*)d_in[18];
    const float* bl2_mu = (const float*)d_in[19];
    const float* Wr2_mu = (const float*)d_in[20];

    int E  = in_sizes[2]; if (E > EMAX_) E = EMAX_;
    int EL = in_sizes[4];
    float* out = (float*)d_out;

    float *bufA, *bufB, *bufC, *bufD, *bufE, *bufF, *c1, *c2;
    int *off_u, *off_m, *deg_u, *deg_m, *adj_u, *adj_m;
    __nv_bfloat16 *wThi, *wTlo;
    cudaGetSymbolAddress((void**)&bufA, g_bufA);
    cudaGetSymbolAddress((void**)&bufB, g_bufB);
    cudaGetSymbolAddress((void**)&bufC, g_bufC);
    cudaGetSymbolAddress((void**)&bufD, g_bufD);
    cudaGetSymbolAddress((void**)&bufE, g_bufE);
    cudaGetSymbolAddress((void**)&bufF, g_bufF);
    cudaGetSymbolAddress((void**)&c1,   g_c1);
    cudaGetSymbolAddress((void**)&c2,   g_c2);
    cudaGetSymbolAddress((void**)&off_u, g_off_u);
    cudaGetSymbolAddress((void**)&off_m, g_off_m);
    cudaGetSymbolAddress((void**)&deg_u, g_deg_u);
    cudaGetSymbolAddress((void**)&deg_m, g_deg_m);
    cudaGetSymbolAddress((void**)&adj_u, g_adj_u);
    cudaGetSymbolAddress((void**)&adj_m, g_adj_m);
    cudaGetSymbolAddress((void**)&wThi, g_wThi);
    cudaGetSymbolAddress((void**)&wTlo, g_wTlo);

    cudaFuncSetAttribute(k_hgemm, cudaFuncAttributeMaxDynamicSharedMemorySize, SM_GEMM_TOT);

    // ---- CSR build ----
    k_zero<<<782, 256>>>();
    k_hist<<<(E + 255) / 256, 256>>>(edge_src, edge_dst, E);
    {
        int nb = 256;
        int chU = (NU_ + nb - 1) / nb;
        k_scanA<<<nb, 1024>>>(deg_u, off_u, NU_, chU);
        k_scanB<<<1, 1024>>>(nb);
        k_scanC<<<(NU_ + 1 + 1023) / 1024, 1024>>>(off_u, NU_, chU, nb);
        int chM = (NM_ + nb - 1) / nb;
        k_scanA<<<nb, 1024>>>(deg_m, off_m, NM_, chM);
        k_scanB<<<1, 1024>>>(nb);
        k_scanC<<<(NM_ + 1 + 1023) / 1024, 1024>>>(off_m, NM_, chM, nb);
    }
    k_fill<<<(E + 255) / 256, 256>>>(edge_src, edge_dst, E);

    // ---- constants + weight prep ----
    k_cvec<<<1, H_>>>(user_init, Wl1_um, Wr1_mu, bl1_mu);
    k_wprep<<<(FD_*128 + 255) / 256, 256>>>(Wm,     FD_, WT_WM);
    k_wprep<<<(H_*128 + 255) / 256, 256>>>(Wr1_um, H_,  WT_R1UM);
    k_wprep<<<(H_*128 + 255) / 256, 256>>>(Wl1_mu, H_,  WT_L1MU);
    k_wprep<<<(H_*128 + 255) / 256, 256>>>(Wr2_um, H_,  WT_R2UM);
    k_wprep<<<(H_*128 + 255) / 256, 256>>>(Wl2_mu, H_,  WT_L2MU);
    k_wprep<<<(H_*128 + 255) / 256, 256>>>(Wl2_um, H_,  WT_L2UM);
    k_wprep<<<(H_*128 + 255) / 256, 256>>>(Wr2_mu, H_,  WT_R2MU);

    int gM = NM_ / 128;               // 625
    int gU = (NU_ + 127) / 128;       // 1563

    // A: movie_x = movie_feats @ Wm + bm
    k_hgemm<<<gM, 256, SM_GEMM_TOT>>>(movie_feats, NM_, FD_, wThi + WT_WM, wTlo + WT_WM,
                                      bufA, 1, bm, nullptr, nullptr, nullptr);
    // C: movie_h = relu(movie_x @ Wr1_um + bl1_um + ind*c1)
    k_hgemm<<<gM, 256, SM_GEMM_TOT>>>(bufA, NM_, H_, wThi + WT_R1UM, wTlo + WT_R1UM,
                                      bufC, 2, bl1_um, c1, deg_m, nullptr);
    // B: movie_p1 = movie_x @ Wl1_mu
    k_hgemm<<<gM, 256, SM_GEMM_TOT>>>(bufA, NM_, H_, wThi + WT_L1MU, wTlo + WT_L1MU,
                                      bufB, 0, nullptr, nullptr, nullptr, nullptr);
    // E: user_h = relu(mean_agg_u(movie_p1) + c2)
    k_agg<<<(NU_ + 7) / 8, 256>>>(off_u, adj_u, bufB, bufE, NU_, 0, c2, nullptr, nullptr);
    // A: movie_r2 = movie_h @ Wr2_um
    k_hgemm<<<gM, 256, SM_GEMM_TOT>>>(bufC, NM_, H_, wThi + WT_R2UM, wTlo + WT_R2UM,
                                      bufA, 0, nullptr, nullptr, nullptr, nullptr);
    // D: movie_p2 = movie_h @ Wl2_mu
    k_hgemm<<<gM, 256, SM_GEMM_TOT>>>(bufC, NM_, H_, wThi + WT_L2MU, wTlo + WT_L2MU,
                                      bufD, 0, nullptr, nullptr, nullptr, nullptr);
    // B: movie_ag = mean_agg_m(user_h)
    k_agg<<<(NM_ + 7) / 8, 256>>>(off_m, adj_m, bufE, bufB, NM_, 1, nullptr, nullptr, nullptr);
    // A: movie_o = movie_ag @ Wl2_um + bl2_um + movie_r2 (in-place add)
    k_hgemm<<<gM, 256, SM_GEMM_TOT>>>(bufB, NM_, H_, wThi + WT_L2UM, wTlo + WT_L2UM,
                                      bufA, 3, bl2_um, nullptr, nullptr, bufA);
    // F: user_r2 = user_h @ Wr2_mu
    k_hgemm<<<gU, 256, SM_GEMM_TOT>>>(bufE, NU_, H_, wThi + WT_R2MU, wTlo + WT_R2MU,
                                      bufF, 0, nullptr, nullptr, nullptr, nullptr);
    // F: user_o = mean_agg_u(movie_p2) + bl2_mu + user_r2 (in-place)
    k_agg<<<(NU_ + 7) / 8, 256>>>(off_u, adj_u, bufD, bufF, NU_, 2, nullptr, bl2_mu, bufF);
    // out
    k_dot<<<(EL + 7) / 8, 256>>>(lbl_user, lbl_movie, bufF, bufA, out, EL);
}

// round 11
// speedup vs baseline: 1.2125x; 1.2125x over previous
#include <cuda_runtime.h>
#include <cuda_bf16.h>
#include <mma.h>
#include <cstdint>

using namespace nvcuda;

#define NU_  200000
#define NM_  80000
#define H_   128
#define FD_  512
#define EMAX_ 2000000

// ======================= scratch =======================
static __device__ float g_bufA[NM_*H_];
static __device__ float g_bufB[NM_*H_];
static __device__ float g_bufC[NM_*H_];
static __device__ float g_bufD[NM_*H_];
static __device__ float g_bufE[NU_*H_];
static __device__ float g_bufF[NU_*H_];

static __device__ int g_off_u[NU_+1];
static __device__ int g_off_m[NM_+1];
static __device__ int g_deg_u[NU_];
static __device__ int g_deg_m[NM_];
static __device__ int g_cur_u[NU_];
static __device__ int g_cur_m[NM_];
static __device__ int g_adj_u[EMAX_];
static __device__ int g_adj_m[EMAX_];
static __device__ float g_c1[H_];
static __device__ float g_c2[H_];
static __device__ int g_bsum[1024];
static __device__ int g_bpre[1026];

// transposed bf16 weights: Wm_T [128,512] then 6 x [128,128] (n-major, k contiguous)
#define WT_WM    0
#define WT_R1UM  (128*512)
#define WT_L1MU  (WT_R1UM + 128*128)
#define WT_R2UM  (WT_L1MU + 128*128)
#define WT_L2MU  (WT_R2UM + 128*128)
#define WT_L2UM  (WT_L2MU + 128*128)
#define WT_R2MU  (WT_L2UM + 128*128)
#define WT_TOT   (WT_R2MU + 128*128)
static __device__ __nv_bfloat16 g_wThi[WT_TOT];
static __device__ __nv_bfloat16 g_wTlo[WT_TOT];

// ======================= graph build =======================
__global__ void k_zero()
{
    int i = blockIdx.x * blockDim.x + threadIdx.x;
    int stride = gridDim.x * blockDim.x;
    for (int j = i; j < NU_; j += stride) { g_deg_u[j] = 0; g_cur_u[j] = 0; }
    for (int j = i; j < NM_; j += stride) { g_deg_m[j] = 0; g_cur_m[j] = 0; }
}

__global__ void k_hist(const int* __restrict__ src, const int* __restrict__ dst, int E)
{
    int i = blockIdx.x * blockDim.x + threadIdx.x;
    int stride = gridDim.x * blockDim.x;
    for (int e = i; e < E; e += stride) {
        atomicAdd(&g_deg_u[src[e]], 1);
        atomicAdd(&g_deg_m[dst[e]], 1);
    }
}

// 3-phase parallel scan
__global__ void __launch_bounds__(1024) k_scanA(const int* __restrict__ deg, int* __restrict__ off,
                                                int n, int chunk)
{
    __shared__ int ws[32];
    int b = blockIdx.x, tid = threadIdx.x, lane = tid & 31, wid = tid >> 5;
    int i = b * chunk + tid;
    int v = (tid < chunk && i < n) ? deg[i] : 0;
    int x = v;
    #pragma unroll
    for (int o = 1; o < 32; o <<= 1) {
        int y = __shfl_up_sync(0xffffffffu, x, o);
        if (lane >= o) x += y;
    }
    if (lane == 31) ws[wid] = x;
    __syncthreads();
    if (wid == 0) {
        int w = ws[lane];
        int xs = w;
        #pragma unroll
        for (int o = 1; o < 32; o <<= 1) {
            int y = __shfl_up_sync(0xffffffffu, xs, o);
            if (lane >= o) xs += y;
        }
        ws[lane] = xs - w;
    }
    __syncthreads();
    int ex = ws[wid] + x - v;
    if (tid < chunk && i < n) off[i] = ex;
    if (tid == 1023) g_bsum[b] = ex + v;
}

__global__ void __launch_bounds__(1024) k_scanB(int nb)
{
    __shared__ int ws[32];
    int tid = threadIdx.x, lane = tid & 31, wid = tid >> 5;
    int v = (tid < nb) ? g_bsum[tid] : 0;
    int x = v;
    #pragma unroll
    for (int o = 1; o < 32; o <<= 1) {
        int y = __shfl_up_sync(0xffffffffu, x, o);
        if (lane >= o) x += y;
    }
    if (lane == 31) ws[wid] = x;
    __syncthreads();
    if (wid == 0) {
        int w = ws[lane];
        int xs = w;
        #pragma unroll
        for (int o = 1; o < 32; o <<= 1) {
            int y = __shfl_up_sync(0xffffffffu, xs, o);
            if (lane >= o) xs += y;
        }
        ws[lane] = xs - w;
    }
    __syncthreads();
    int ex = ws[wid] + x - v;
    if (tid < nb) g_bpre[tid] = ex;
    if (tid == 1023) g_bpre[nb] = ex + v;
}

__global__ void k_scanC(int* __restrict__ off, int n, int chunk, int nb)
{
    int i = blockIdx.x * blockDim.x + threadIdx.x;
    if (i < n) off[i] += g_bpre[i / chunk];
    else if (i == n) off[n] = g_bpre[nb];
}

__global__ void k_fill(const int* __restrict__ src, const int* __restrict__ dst, int E)
{
    int i = blockIdx.x * blockDim.x + threadIdx.x;
    int stride = gridDim.x * blockDim.x;
    for (int e = i; e < E; e += stride) {
        int s = src[e], d = dst[e];
        int pm = g_off_m[d] + atomicAdd(&g_cur_m[d], 1);
        g_adj_m[pm] = s;
        int pu = g_off_u[s] + atomicAdd(&g_cur_u[s], 1);
        g_adj_u[pu] = d;
    }
}

// ======================= tiny precompute =======================
__global__ void k_cvec(const float* __restrict__ u0,
                       const float* __restrict__ Wl1um,
                       const float* __restrict__ Wr1mu,
                       const float* __restrict__ bl1mu)
{
    int c = threadIdx.x;
    float s1 = 0.f, s2 = 0.f;
    #pragma unroll 8
    for (int k = 0; k < H_; k++) {
        float u = u0[k];
        s1 += u * Wl1um[k * H_ + c];
        s2 += u * Wr1mu[k * H_ + c];
    }
    g_c1[c] = s1;
    g_c2[c] = bl1mu[c] + s2;
}

// transpose+split fp32 weight W[K,128] -> hi/lo bf16 [128,K] (n-major)
__global__ void k_wprep(const float* __restrict__ W, int K, int dstOff)
{
    int i = blockIdx.x * blockDim.x + threadIdx.x;
    if (i >= K * 128) return;
    int n = i & 127, k = i >> 7;
    float x = W[k * 128 + n];
    __nv_bfloat16 h = __float2bfloat16(x);
    float r = x - __bfloat162float(h);
    g_wThi[dstOff + (size_t)n * K + k] = h;
    g_wTlo[dstOff + (size_t)n * K + k] = __float2bfloat16(r);
}

// ======================= wmma bf16 split GEMM (B staged in smem) =======================
// C[M,128] = A[M,K] @ W[K,128]; A fp32, W pre-split hi/lo bf16, transposed [128,K].
// D = Ahi*Whi + Ahi*Wlo + Alo*Whi, fp32 accumulate.
// Block tile 128x128, 8 warps of 32x64. K chunked by 64: A converted to smem, B copied to smem.
// mode 0: raw; 1: +bias; 2: relu(+bias+(deg>0)*cvec); 3: +bias+addM (addM may alias C)
#define LDA 72                     // bf16 elems per smem row (64 + 8 pad)
#define SM_A_HI   0
#define SM_A_LO   (128 * LDA * 2)              // 18432
#define SM_B_HI   (2 * 128 * LDA * 2)          // 36864
#define SM_B_LO   (3 * 128 * LDA * 2)          // 55296
#define SM_GEMM_TOT (4 * 128 * LDA * 2)        // 73728 (epilogue 64KB float region overlaps)

__global__ void __launch_bounds__(256) k_hgemm(
    const float* __restrict__ A, int M, int K,
    const __nv_bfloat16* __restrict__ WThi, const __nv_bfloat16* __restrict__ WTlo,
    float* __restrict__ C, int mode,
    const float* __restrict__ bias, const float* __restrict__ cvec,
    const int* __restrict__ deg, const float* __restrict__ addM)
{
    extern __shared__ char smem[];
    __nv_bfloat16* sAhi = (__nv_bfloat16*)(smem + SM_A_HI);
    __nv_bfloat16* sAlo = (__nv_bfloat16*)(smem + SM_A_LO);
    __nv_bfloat16* sBhi = (__nv_bfloat16*)(smem + SM_B_HI);
    __nv_bfloat16* sBlo = (__nv_bfloat16*)(smem + SM_B_LO);
    float* sC = (float*)smem;

    int t = threadIdx.x;
    int wid = t >> 5;
    int warp_m = wid & 3;          // rows warp_m*32
    int warp_n = wid >> 2;         // cols warp_n*64
    int rowBase = blockIdx.x * 128;

    wmma::fragment<wmma::accumulator, 16, 16, 16, float> acc[2][4];
    #pragma unroll
    for (int i = 0; i < 2; i++)
        #pragma unroll
        for (int j = 0; j < 4; j++) wmma::fill_fragment(acc[i][j], 0.0f);

    int lrow = t >> 1;                 // 0..127
    int lcb  = (t & 1) * 32;           // 0 or 32
    int grow = rowBase + lrow;
    bool arowOk = grow < M;
    const float* Arow = A + (size_t)grow * K;
    const __nv_bfloat16* Bh = WThi + (size_t)lrow * K;   // lrow = n index for B
    const __nv_bfloat16* Bl = WTlo + (size_t)lrow * K;

    int nch = K >> 6;
    for (int ch = 0; ch < nch; ch++) {
        int k0 = ch * 64;
        // ---- A chunk: 128 x 64 fp32 -> hi/lo bf16 smem ----
        #pragma unroll
        for (int j = 0; j < 8; j++) {
            int col = lcb + j * 4;
            float4 v = arowOk ? *(const float4*)(Arow + k0 + col)
                              : make_float4(0.f, 0.f, 0.f, 0.f);
            __nv_bfloat162 h01, h23, l01, l23;
            h01.x = __float2bfloat16(v.x); h01.y = __float2bfloat16(v.y);
            h23.x = __float2bfloat16(v.z); h23.y = __float2bfloat16(v.w);
            l01.x = __float2bfloat16(v.x - __bfloat162float(h01.x));
            l01.y = __float2bfloat16(v.y - __bfloat162float(h01.y));
            l23.x = __float2bfloat16(v.z - __bfloat162float(h23.x));
            l23.y = __float2bfloat16(v.w - __bfloat162float(h23.y));
            int base = lrow * LDA + col;
            *(__nv_bfloat162*)&sAhi[base]     = h01;
            *(__nv_bfloat162*)&sAhi[base + 2] = h23;
            *(__nv_bfloat162*)&sAlo[base]     = l01;
            *(__nv_bfloat162*)&sAlo[base + 2] = l23;
        }
        // ---- B chunk: 128(n) x 64(k) hi/lo bf16 -> smem (n-major = col_major, ld=LDA) ----
        {
            int base = lrow * LDA + lcb;
            uint4 h0 = *(const uint4*)(Bh + k0 + lcb);
            uint4 h1 = *(const uint4*)(Bh + k0 + lcb + 8);
            uint4 h2 = *(const uint4*)(Bh + k0 + lcb + 16);
            uint4 h3 = *(const uint4*)(Bh + k0 + lcb + 24);
            *(uint4*)&sBhi[base]      = h0;
            *(uint4*)&sBhi[base + 8]  = h1;
            *(uint4*)&sBhi[base + 16] = h2;
            *(uint4*)&sBhi[base + 24] = h3;
            uint4 l0 = *(const uint4*)(Bl + k0 + lcb);
            uint4 l1 = *(const uint4*)(Bl + k0 + lcb + 8);
            uint4 l2 = *(const uint4*)(Bl + k0 + lcb + 16);
            uint4 l3 = *(const uint4*)(Bl + k0 + lcb + 24);
            *(uint4*)&sBlo[base]      = l0;
            *(uint4*)&sBlo[base + 8]  = l1;
            *(uint4*)&sBlo[base + 16] = l2;
            *(uint4*)&sBlo[base + 24] = l3;
        }
        __syncthreads();

        // ---- 4 k-steps of 16 ----
        #pragma unroll
        for (int ks = 0; ks < 4; ks++) {
            int kk = ks * 16;
            wmma::fragment<wmma::matrix_a, 16, 16, 16, __nv_bfloat16, wmma::row_major> ah[2], al[2];
            wmma::fragment<wmma::matrix_b, 16, 16, 16, __nv_bfloat16, wmma::col_major> bh[4], bl[4];
            #pragma unroll
            for (int i = 0; i < 2; i++) {
                int r0 = warp_m * 32 + i * 16;
                wmma::load_matrix_sync(ah[i], &sAhi[r0 * LDA + kk], LDA);
                wmma::load_matrix_sync(al[i], &sAlo[r0 * LDA + kk], LDA);
            }
            #pragma unroll
            for (int j = 0; j < 4; j++) {
                int n0 = warp_n * 64 + j * 16;
                wmma::load_matrix_sync(bh[j], &sBhi[n0 * LDA + kk], LDA);
                wmma::load_matrix_sync(bl[j], &sBlo[n0 * LDA + kk], LDA);
            }
            #pragma unroll
            for (int i = 0; i < 2; i++)
                #pragma unroll
                for (int j = 0; j < 4; j++) {
                    wmma::mma_sync(acc[i][j], ah[i], bh[j], acc[i][j]);
                    wmma::mma_sync(acc[i][j], ah[i], bl[j], acc[i][j]);
                    wmma::mma_sync(acc[i][j], al[i], bh[j], acc[i][j]);
                }
        }
        __syncthreads();
    }

    // ---- epilogue: stage accumulators to smem, then modes ----
    #pragma unroll
    for (int i = 0; i < 2; i++)
        #pragma unroll
        for (int j = 0; j < 4; j++) {
            int r0 = warp_m * 32 + i * 16;
            int n0 = warp_n * 64 + j * 16;
            wmma::store_matrix_sync(&sC[r0 * 128 + n0], acc[i][j], 128, wmma::mem_row_major);
        }
    __syncthreads();

    int erow = t >> 1;
    int ecb  = (t & 1) * 64;
    int growE = rowBase + erow;
    if (growE < M) {
        float ind = 0.f;
        if (mode == 2) ind = (deg[growE] > 0) ? 1.f : 0.f;
        #pragma unroll
        for (int j = 0; j < 16; j++) {
            int c = ecb + j * 4;
            float4 o = *(float4*)&sC[erow * 128 + c];
            if (mode == 1) {
                float4 b4 = *(const float4*)&bias[c];
                o.x += b4.x; o.y += b4.y; o.z += b4.z; o.w += b4.w;
            } else if (mode == 2) {
                float4 b4 = *(const float4*)&bias[c];
                float4 cv = *(const float4*)&cvec[c];
                o.x = fmaxf(o.x + b4.x + ind * cv.x, 0.f);
                o.y = fmaxf(o.y + b4.y + ind * cv.y, 0.f);
                o.z = fmaxf(o.z + b4.z + ind * cv.z, 0.f);
                o.w = fmaxf(o.w + b4.w + ind * cv.w, 0.f);
            } else if (mode == 3) {
                float4 b4 = *(const float4*)&bias[c];
                float4 a2 = *(const float4*)&addM[(size_t)growE * 128 + c];
                o.x += b4.x + a2.x; o.y += b4.y + a2.y;
                o.z += b4.z + a2.z; o.w += b4.w + a2.w;
            }
            *(float4*)&C[(size_t)growE * 128 + c] = o;
        }
    }
}

// ======================= mean aggregation =======================
__global__ void __launch_bounds__(256) k_agg(
    const int* __restrict__ off, const int* __restrict__ adj,
    const float* __restrict__ X, float* __restrict__ out, int n, int mode,
    const float* __restrict__ cvec, const float* __restrict__ bias,
    const float* __restrict__ addM)
{
    int node = blockIdx.x * 8 + (threadIdx.x >> 5);
    int lane = threadIdx.x & 31;
    if (node >= n) return;
    int s = off[node], e = off[node + 1];
    float4 a0 = make_float4(0.f, 0.f, 0.f, 0.f);
    float4 a1 = make_float4(0.f, 0.f, 0.f, 0.f);
    int p = s;
    for (; p + 1 < e; p += 2) {
        int m0 = __ldg(&adj[p]);
        int m1 = __ldg(&adj[p + 1]);
        float4 v0 = *(const float4*)&X[(size_t)m0 * 128 + lane * 4];
        float4 v1 = *(const float4*)&X[(size_t)m1 * 128 + lane * 4];
        a0.x += v0.x; a0.y += v0.y; a0.z += v0.z; a0.w += v0.w;
        a1.x += v1.x; a1.y += v1.y; a1.z += v1.z; a1.w += v1.w;
    }
    if (p < e) {
        int m0 = __ldg(&adj[p]);
        float4 v0 = *(const float4*)&X[(size_t)m0 * 128 + lane * 4];
        a0.x += v0.x; a0.y += v0.y; a0.z += v0.z; a0.w += v0.w;
    }
    float4 acc = make_float4(a0.x + a1.x, a0.y + a1.y, a0.z + a1.z, a0.w + a1.w);
    float inv = (e > s) ? 1.f / (float)(e - s) : 0.f;
    acc.x *= inv; acc.y *= inv; acc.z *= inv; acc.w *= inv;

    float4 o = acc;
    if (mode == 0) {
        float4 c = *(const float4*)&cvec[lane * 4];
        o.x = fmaxf(acc.x + c.x, 0.f);
        o.y = fmaxf(acc.y + c.y, 0.f);
        o.z = fmaxf(acc.z + c.z, 0.f);
        o.w = fmaxf(acc.w + c.w, 0.f);
    } else if (mode == 2) {
        float4 b = *(const float4*)&bias[lane * 4];
        float4 a2 = *(const float4*)&addM[(size_t)node * 128 + lane * 4];
        o.x = acc.x + b.x + a2.x;
        o.y = acc.y + b.y + a2.y;
        o.z = acc.z + b.z + a2.z;
        o.w = acc.w + b.w + a2.w;
    }
    *(float4*)&out[(size_t)node * 128 + lane * 4] = o;
}

// ======================= final edge dot =======================
__global__ void __launch_bounds__(256) k_dot(
    const int* __restrict__ lu, const int* __restrict__ lm,
    const float* __restrict__ U, const float* __restrict__ Mo,
    float* __restrict__ out, int n)
{
    int e = blockIdx.x * 8 + (threadIdx.x >> 5);
    int lane = threadIdx.x & 31;
    if (e >= n) return;
    int u = lu[e], m = lm[e];
    float4 a = *(const float4*)&U [(size_t)u * 128 + lane * 4];
    float4 b = *(const float4*)&Mo[(size_t)m * 128 + lane * 4];
    float p = a.x * b.x + a.y * b.y + a.z * b.z + a.w * b.w;
    #pragma unroll
    for (int o = 16; o > 0; o >>= 1) p += __shfl_xor_sync(0xffffffffu, p, o);
    if (lane == 0) out[e] = p;
}

// ======================= launch =======================
extern "C" void kernel_launch(void* const* d_in, const int* in_sizes, int n_in,
                              void* d_out, int out_size)
{
    const float* movie_feats = (const float*)d_in[0];
    const float* user_init   = (const float*)d_in[1];
    const int*   edge_src    = (const int*)d_in[2];
    const int*   edge_dst    = (const int*)d_in[3];
    const int*   lbl_user    = (const int*)d_in[4];
    const int*   lbl_movie   = (const int*)d_in[5];
    const float* Wm     = (const float*)d_in[7];
    const float* bm     = (const float*)d_in[8];
    const float* Wl1_um = (const float*)d_in[9];
    const float* bl1_um = (const float*)d_in[10];
    const float* Wr1_um = (const float*)d_in[11];
    const float* Wl1_mu = (const float*)d_in[12];
    const float* bl1_mu = (const float*)d_in[13];
    const float* Wr1_mu = (const float*)d_in[14];
    const float* Wl2_um = (const float*)d_in[15];
    const float* bl2_um = (const float*)d_in[16];
    const float* Wr2_um = (const float*)d_in[17];
    const float* Wl2_mu = (const float*)d_in[18];
    const float* bl2_mu = (const float*)d_in[19];
    const float* Wr2_mu = (const float*)d_in[20];

    int E  = in_sizes[2]; if (E > EMAX_) E = EMAX_;
    int EL = in_sizes[4];
    float* out = (float*)d_out;

    float *bufA, *bufB, *bufC, *bufD, *bufE, *bufF, *c1, *c2;
    int *off_u, *off_m, *deg_u, *deg_m, *adj_u, *adj_m;
    __nv_bfloat16 *wThi, *wTlo;
    cudaGetSymbolAddress((void**)&bufA, g_bufA);
    cudaGetSymbolAddress((void**)&bufB, g_bufB);
    cudaGetSymbolAddress((void**)&bufC, g_bufC);
    cudaGetSymbolAddress((void**)&bufD, g_bufD);
    cudaGetSymbolAddress((void**)&bufE, g_bufE);
    cudaGetSymbolAddress((void**)&bufF, g_bufF);
    cudaGetSymbolAddress((void**)&c1,   g_c1);
    cudaGetSymbolAddress((void**)&c2,   g_c2);
    cudaGetSymbolAddress((void**)&off_u, g_off_u);
    cudaGetSymbolAddress((void**)&off_m, g_off_m);
    cudaGetSymbolAddress((void**)&deg_u, g_deg_u);
    cudaGetSymbolAddress((void**)&deg_m, g_deg_m);
    cudaGetSymbolAddress((void**)&adj_u, g_adj_u);
    cudaGetSymbolAddress((void**)&adj_m, g_adj_m);
    cudaGetSymbolAddress((void**)&wThi, g_wThi);
    cudaGetSymbolAddress((void**)&wTlo, g_wTlo);

    cudaFuncSetAttribute(k_hgemm, cudaFuncAttributeMaxDynamicSharedMemorySize, SM_GEMM_TOT);

    // ---- CSR build ----
    k_zero<<<782, 256>>>();
    k_hist<<<(E + 255) / 256, 256>>>(edge_src, edge_dst, E);
    {
        int nb = 256;
        int chU = (NU_ + nb - 1) / nb;
        k_scanA<<<nb, 1024>>>(deg_u, off_u, NU_, chU);
        k_scanB<<<1, 1024>>>(nb);
        k_scanC<<<(NU_ + 1 + 1023) / 1024, 1024>>>(off_u, NU_, chU, nb);
        int chM = (NM_ + nb - 1) / nb;
        k_scanA<<<nb, 1024>>>(deg_m, off_m, NM_, chM);
        k_scanB<<<1, 1024>>>(nb);
        k_scanC<<<(NM_ + 1 + 1023) / 1024, 1024>>>(off_m, NM_, chM, nb);
    }
    k_fill<<<(E + 255) / 256, 256>>>(edge_src, edge_dst, E);

    // ---- constants + weight prep ----
    k_cvec<<<1, H_>>>(user_init, Wl1_um, Wr1_mu, bl1_mu);
    k_wprep<<<(FD_*128 + 255) / 256, 256>>>(Wm,     FD_, WT_WM);
    k_wprep<<<(H_*128 + 255) / 256, 256>>>(Wr1_um, H_,  WT_R1UM);
    k_wprep<<<(H_*128 + 255) / 256, 256>>>(Wl1_mu, H_,  WT_L1MU);
    k_wprep<<<(H_*128 + 255) / 256, 256>>>(Wr2_um, H_,  WT_R2UM);
    k_wprep<<<(H_*128 + 255) / 256, 256>>>(Wl2_mu, H_,  WT_L2MU);
    k_wprep<<<(H_*128 + 255) / 256, 256>>>(Wl2_um, H_,  WT_L2UM);
    k_wprep<<<(H_*128 + 255) / 256, 256>>>(Wr2_mu, H_,  WT_R2MU);

    int gM = NM_ / 128;               // 625
    int gU = (NU_ + 127) / 128;       // 1563

    // A: movie_x = movie_feats @ Wm + bm
    k_hgemm<<<gM, 256, SM_GEMM_TOT>>>(movie_feats, NM_, FD_, wThi + WT_WM, wTlo + WT_WM,
                                      bufA, 1, bm, nullptr, nullptr, nullptr);
    // C: movie_h = relu(movie_x @ Wr1_um + bl1_um + ind*c1)
    k_hgemm<<<gM, 256, SM_GEMM_TOT>>>(bufA, NM_, H_, wThi + WT_R1UM, wTlo + WT_R1UM,
                                      bufC, 2, bl1_um, c1, deg_m, nullptr);
    // B: movie_p1 = movie_x @ Wl1_mu
    k_hgemm<<<gM, 256, SM_GEMM_TOT>>>(bufA, NM_, H_, wThi + WT_L1MU, wTlo + WT_L1MU,
                                      bufB, 0, nullptr, nullptr, nullptr, nullptr);
    // E: user_h = relu(mean_agg_u(movie_p1) + c2)
    k_agg<<<(NU_ + 7) / 8, 256>>>(off_u, adj_u, bufB, bufE, NU_, 0, c2, nullptr, nullptr);
    // A: movie_r2 = movie_h @ Wr2_um
    k_hgemm<<<gM, 256, SM_GEMM_TOT>>>(bufC, NM_, H_, wThi + WT_R2UM, wTlo + WT_R2UM,
                                      bufA, 0, nullptr, nullptr, nullptr, nullptr);
    // D: movie_p2 = movie_h @ Wl2_mu
    k_hgemm<<<gM, 256, SM_GEMM_TOT>>>(bufC, NM_, H_, wThi + WT_L2MU, wTlo + WT_L2MU,
                                      bufD, 0, nullptr, nullptr, nullptr, nullptr);
    // B: movie_ag = mean_agg_m(user_h)
    k_agg<<<(NM_ + 7) / 8, 256>>>(off_m, adj_m, bufE, bufB, NM_, 1, nullptr, nullptr, nullptr);
    // A: movie_o = movie_ag @ Wl2_um + bl2_um + movie_r2 (in-place add)
    k_hgemm<<<gM, 256, SM_GEMM_TOT>>>(bufB, NM_, H_, wThi + WT_L2UM, wTlo + WT_L2UM,
                                      bufA, 3, bl2_um, nullptr, nullptr, bufA);
    // F: user_r2 = user_h @ Wr2_mu
    k_hgemm<<<gU, 256, SM_GEMM_TOT>>>(bufE, NU_, H_, wThi + WT_R2MU, wTlo + WT_R2MU,
                                      bufF, 0, nullptr, nullptr, nullptr, nullptr);
    // F: user_o = mean_agg_u(movie_p2) + bl2_mu + user_r2 (in-place)
    k_agg<<<(NU_ + 7) / 8, 256>>>(off_u, adj_u, bufD, bufF, NU_, 2, nullptr, bl2_mu, bufF);
    // out
    k_dot<<<(EL + 7) / 8, 256>>>(lbl_user, lbl_movie, bufF, bufA, out, EL);
}